// round 16
// baseline (speedup 1.0000x reference)
#include <cuda_runtime.h>
#include <math.h>

#define HH 224
#define WW 224
#define BB 2
#define PP 2048
#define FF 256
#define SIGMA_F 0.0003f
#define INV_SIGMA 3333.3333333f
// Drop faces whose prob p = exp(-d2/sigma) < 1e-6: each omitted factor
// perturbs prod by < 1e-6 relative; worst case over <= 256 faces < 2.6e-4,
// vs the 1e-3 norm-relative threshold (realistically ~1e-5).
#define D2CUT 0.0041447f             // sigma * ln(1e6)
#define MARGIN 0.0643793f            // sqrt(D2CUT)

struct MergeRec { float z, l0, l1, pr; int bi; };

__device__ __forceinline__ void edge_dist(float px, float py, float4 v3,
                                          float4 v4, float4 v5, float4 v6,
                                          float x2, float y2, float& prod)
{
    float pax = px - v3.x, pay = py - v3.y;                 // from v0
    float t = fminf(fmaxf((pax*v4.x + pay*v4.y)*v4.z, 0.0f), 1.0f);
    float ddx = pax - t*v4.x, ddy = pay - t*v4.y;
    float d2 = ddx*ddx + ddy*ddy;

    pax = px - v3.z; pay = py - v3.w;                       // from v1
    t = fminf(fmaxf((pax*v5.x + pay*v5.y)*v5.z, 0.0f), 1.0f);
    ddx = pax - t*v5.x; ddy = pay - t*v5.y;
    d2 = fminf(d2, ddx*ddx + ddy*ddy);

    pax = px - x2; pay = py - y2;                           // from v2
    t = fminf(fmaxf((pax*v6.x + pay*v6.y)*v6.z, 0.0f), 1.0f);
    ddx = pax - t*v6.x; ddy = pay - t*v6.y;
    d2 = fminf(d2, ddx*ddx + ddy*ddy);

    if (d2 < D2CUT) {
        float p = __expf(-d2 * INV_SIGMA) * (1.0f - 1e-7f);
        prod *= fmaxf(1.0f - p, 0.0f);
    }
}

// ---------------------------------------------------------------------------
// Fused kernel: 256 threads/block, 16x8 tile, grid (14, 28, BB).
// Phase 1: thread f computes face f's transform, culls (front & bbox+margin),
//          order-preserving compaction straight into smem.
// Phase 2: 64 pixel-pairs x 4 face-quarters (contiguous ranges).
// Phase 3: quarter merge (buffers overlaid on sf_hot), color gather via vi.
// __launch_bounds__(256, 6): cap regs at 42 so 6 CTAs fit per SM
// (65536/(42*256) = 6.1) -> 888 resident slots for 784 blocks = one wave.
// ---------------------------------------------------------------------------
__global__ void __launch_bounds__(256, 6) vcr_fused_kernel(
    const float* __restrict__ pts,
    const int*   __restrict__ faces,
    const float* __restrict__ rot,
    const float* __restrict__ pos,
    const float* __restrict__ proj,
    const float* __restrict__ cols,
    float* __restrict__ out)
{
    __shared__ float4 sf_hot[FF * 3];     // 12 KB; reused as MergeRec after loop
    __shared__ float4 sf_edge[FF * 4];    // 16 KB
    __shared__ int4   svi[FF];            // 4 KB: vertex indices per slot
    __shared__ int    warp_off[8];
    __shared__ int    sm_cnt;

    int b   = blockIdx.z;
    int tid = threadIdx.x;

    int tx0 = blockIdx.x * 16;
    int ty0 = blockIdx.y * 8;
    float txmin = (2.0f*tx0 + 1.0f) * (1.0f/WW) - 1.0f;
    float txmax = (2.0f*(tx0+15) + 1.0f) * (1.0f/WW) - 1.0f;
    float tymax = 1.0f - (2.0f*ty0 + 1.0f) * (1.0f/HH);
    float tymin = 1.0f - (2.0f*(ty0+7) + 1.0f) * (1.0f/HH);

    // ---------------- Phase 1: per-face prep + cull + compact ----------------
    {
        int f = tid;
        float R0 = __ldg(&rot[b*9+0]), R1 = __ldg(&rot[b*9+1]), R2 = __ldg(&rot[b*9+2]);
        float R3 = __ldg(&rot[b*9+3]), R4 = __ldg(&rot[b*9+4]), R5 = __ldg(&rot[b*9+5]);
        float R6 = __ldg(&rot[b*9+6]), R7 = __ldg(&rot[b*9+7]), R8 = __ldg(&rot[b*9+8]);
        float cpx = __ldg(&pos[b*3+0]), cpy = __ldg(&pos[b*3+1]), cpz = __ldg(&pos[b*3+2]);
        float pr0 = __ldg(&proj[0]), pr1 = __ldg(&proj[1]), pr2 = __ldg(&proj[2]);

        int vi0 = __ldg(&faces[f*3+0]);
        int vi1 = __ldg(&faces[f*3+1]);
        int vi2 = __ldg(&faces[f*3+2]);
        int vi[3] = { vi0, vi1, vi2 };

        float Pz[3], Qx[3], Qy[3];
        float nx, ny, nz;
        {
            float Px[3], Py[3];
            #pragma unroll
            for (int k = 0; k < 3; k++) {
                const float* pp = pts + ((size_t)b * PP + vi[k]) * 3;
                float dx = __ldg(pp+0)-cpx, dy = __ldg(pp+1)-cpy, dz = __ldg(pp+2)-cpz;
                float cx = R0*dx + R1*dy + R2*dz;
                float cy = R3*dx + R4*dy + R5*dz;
                float cw = R6*dx + R7*dy + R8*dz;
                Px[k]=cx; Py[k]=cy; Pz[k]=cw;
                float zz = cw * pr2;
                Qx[k] = (cx*pr0)/zz;
                Qy[k] = (cy*pr1)/zz;
            }
            float ux=Px[1]-Px[0], uy=Py[1]-Py[0], uz=Pz[1]-Pz[0];
            float vx=Px[2]-Px[0], vy=Py[2]-Py[0], vz=Pz[2]-Pz[0];
            nx = uy*vz - uz*vy;
            ny = uz*vx - ux*vz;
            nz = ux*vy - uy*vx;
        }

        if (blockIdx.x == 0 && blockIdx.y == 0) {
            float inv = 1.0f / sqrtf(nx*nx + ny*ny + nz*nz + 1e-10f);
            size_t noff = (size_t)BB*HH*WW*3 + (size_t)BB*HH*WW + ((size_t)b*FF + f)*3;
            out[noff+0] = nx*inv;
            out[noff+1] = ny*inv;
            out[noff+2] = nz*inv;
        }

        float bxmin = fminf(Qx[0], fminf(Qx[1], Qx[2]));
        float bxmax = fmaxf(Qx[0], fmaxf(Qx[1], Qx[2]));
        float bymin = fminf(Qy[0], fminf(Qy[1], Qy[2]));
        float bymax = fmaxf(Qy[0], fmaxf(Qy[1], Qy[2]));
        bool keep = (nz > 0.0f) &
                    (bxmin - MARGIN <= txmax) & (bxmax + MARGIN >= txmin) &
                    (bymin - MARGIN <= tymax) & (bymax + MARGIN >= tymin);

        unsigned mask = __ballot_sync(0xffffffffu, keep);
        int lane = tid & 31, wid = tid >> 5;
        if (lane == 0) warp_off[wid] = __popc(mask);
        __syncthreads();
        if (tid == 0) {
            int s = 0;
            #pragma unroll
            for (int i = 0; i < 8; i++) { int t = warp_off[i]; warp_off[i] = s; s += t; }
            sm_cnt = s;
        }
        __syncthreads();

        if (keep) {
            int slot = warp_off[wid] + __popc(mask & ((1u << lane) - 1u));

            float denom = (Qy[1]-Qy[2])*(Qx[0]-Qx[2]) + (Qx[2]-Qx[1])*(Qy[0]-Qy[2]);
            if (fabsf(denom) < 1e-10f) denom = 1e-10f;
            float invden = 1.0f / denom;
            float den2 = denom * denom;

            float e01x = Qx[1]-Qx[0], e01y = Qy[1]-Qy[0];
            float e12x = Qx[2]-Qx[1], e12y = Qy[2]-Qy[1];
            float e20x = Qx[0]-Qx[2], e20y = Qy[0]-Qy[2];
            float i01 = 1.0f/(e01x*e01x + e01y*e01y + 1e-10f);
            float i12 = 1.0f/(e12x*e12x + e12y*e12y + 1e-10f);
            float i20 = 1.0f/(e20x*e20x + e20y*e20y + 1e-10f);

            sf_hot[slot*3+0] = make_float4(Qx[2], Qy[2], (Qy[1]-Qy[2])*invden, (Qx[2]-Qx[1])*invden);
            sf_hot[slot*3+1] = make_float4((Qy[2]-Qy[0])*invden, (Qx[0]-Qx[2])*invden, Pz[0], Pz[1]);
            sf_hot[slot*3+2] = make_float4(Pz[2], den2*i12, den2*i20, den2*i01);
            sf_edge[slot*4+0] = make_float4(Qx[0], Qy[0], Qx[1], Qy[1]);
            sf_edge[slot*4+1] = make_float4(e01x, e01y, i01, 0.0f);
            sf_edge[slot*4+2] = make_float4(e12x, e12y, i12, 0.0f);
            sf_edge[slot*4+3] = make_float4(e20x, e20y, i20, 0.0f);
            svi[slot] = make_int4(vi0, vi1, vi2, 0);
        }
    }
    __syncthreads();
    int m = sm_cnt;

    // ---------------- Phase 2: render 2 px/thread, quarter face ranges -------
    int quarter = tid >> 6;            // 0..3
    int p       = tid & 63;            // pixel pair
    int xa = tx0 + (p & 7) * 2;
    int y  = ty0 + (p >> 3);
    float pxa = (2.0f*xa + 1.0f) * (1.0f/WW) - 1.0f;
    float pxb = pxa + 2.0f*(1.0f/WW);
    float py  = 1.0f - (2.0f*y + 1.0f) * (1.0f/HH);

    const float IN_F = 1.0f - (1.0f - 1e-7f);   // exact (Sterbenz)

    int ibeg = (m * quarter) >> 2;
    int iend = (m * (quarter + 1)) >> 2;

    float besta = -1e10f, bestb = -1e10f;
    int   bia = -1, bib = -1;
    float bl0a = 0.0f, bl1a = 0.0f, bl0b = 0.0f, bl1b = 0.0f;
    float proda = 1.0f, prodb = 1.0f;

    #pragma unroll 2
    for (int i = ibeg; i < iend; i++) {
        float4 v0 = sf_hot[i*3+0];
        float4 v1 = sf_hot[i*3+1];
        float4 v2 = sf_hot[i*3+2];

        float dy  = py  - v0.y;
        float dxa = pxa - v0.x;
        float dxb = pxb - v0.x;
        float t0 = v0.w * dy;
        float t1 = v1.y * dy;
        float l0a = fmaf(v0.z, dxa, t0);
        float l0b = fmaf(v0.z, dxb, t0);
        float l1a = fmaf(v1.x, dxa, t1);
        float l1b = fmaf(v1.x, dxb, t1);
        float l2a = 1.0f - l0a - l1a;
        float l2b = 1.0f - l0b - l1b;

        bool ina = fminf(l0a, fminf(l1a, l2a)) >= 0.0f;
        bool inb = fminf(l0b, fminf(l1b, l2b)) >= 0.0f;
        bool needa = false, needb = false;

        if (ina) {
            float z = l0a*v1.z + l1a*v1.w + l2a*v2.x;
            if (z > besta) { besta = z; bia = i; bl0a = l0a; bl1a = l1a; }
            proda *= IN_F;
        } else {
            float lb2 = 0.0f;
            if (l0a < 0.0f) lb2 = l0a*l0a*v2.y;
            if (l1a < 0.0f) lb2 = fmaxf(lb2, l1a*l1a*v2.z);
            if (l2a < 0.0f) lb2 = fmaxf(lb2, l2a*l2a*v2.w);
            needa = lb2 < D2CUT;
        }
        if (inb) {
            float z = l0b*v1.z + l1b*v1.w + l2b*v2.x;
            if (z > bestb) { bestb = z; bib = i; bl0b = l0b; bl1b = l1b; }
            prodb *= IN_F;
        } else {
            float lb2 = 0.0f;
            if (l0b < 0.0f) lb2 = l0b*l0b*v2.y;
            if (l1b < 0.0f) lb2 = fmaxf(lb2, l1b*l1b*v2.z);
            if (l2b < 0.0f) lb2 = fmaxf(lb2, l2b*l2b*v2.w);
            needb = lb2 < D2CUT;
        }

        if (needa | needb) {
            float4 v3 = sf_edge[i*4+0];
            float4 v4 = sf_edge[i*4+1];
            float4 v5 = sf_edge[i*4+2];
            float4 v6 = sf_edge[i*4+3];
            if (needa) edge_dist(pxa, py, v3, v4, v5, v6, v0.x, v0.y, proda);
            if (needb) edge_dist(pxb, py, v3, v4, v5, v6, v0.x, v0.y, prodb);
        }
    }

    // ---------------- Phase 3: merge (buffers overlay sf_hot) ----------------
    MergeRec* mrec = (MergeRec*)sf_hot;   // 384 recs * 20 B = 7.7 KB <= 12 KB
    __syncthreads();                      // all loop reads of sf_hot done
    if (quarter > 0) {
        int base = (quarter - 1) * 128;
        mrec[base + p]      = { besta, bl0a, bl1a, proda, bia };
        mrec[base + 64 + p] = { bestb, bl0b, bl1b, prodb, bib };
    }
    __syncthreads();
    if (quarter == 0) {
        #pragma unroll
        for (int k = 0; k < 3; k++) {
            MergeRec ra = mrec[k*128 + p];
            if (ra.z > besta) { besta = ra.z; bia = ra.bi; bl0a = ra.l0; bl1a = ra.l1; }
            proda *= ra.pr;
            MergeRec rb = mrec[k*128 + 64 + p];
            if (rb.z > bestb) { bestb = rb.z; bib = rb.bi; bl0b = rb.l0; bl1b = rb.l1; }
            prodb *= rb.pr;
        }

        #pragma unroll
        for (int j = 0; j < 2; j++) {
            int   bi  = j ? bib : bia;
            float bl0 = j ? bl0b : bl0a;
            float bl1 = j ? bl1b : bl1a;
            float pr  = j ? prodb : proda;
            float r = 0.0f, g = 0.0f, bcol = 0.0f;
            if (bi >= 0) {
                float bl2 = 1.0f - bl0 - bl1;
                int4 vi = svi[bi];
                const float* c0 = cols + ((size_t)b * PP + vi.x) * 3;
                const float* c1 = cols + ((size_t)b * PP + vi.y) * 3;
                const float* c2 = cols + ((size_t)b * PP + vi.z) * 3;
                r    = bl0*__ldg(c0+0) + bl1*__ldg(c1+0) + bl2*__ldg(c2+0);
                g    = bl0*__ldg(c0+1) + bl1*__ldg(c1+1) + bl2*__ldg(c2+1);
                bcol = bl0*__ldg(c0+2) + bl1*__ldg(c1+2) + bl2*__ldg(c2+2);
            }
            int x = xa + j;
            size_t ro = ((size_t)(b*HH + y)*WW + x)*3;
            out[ro+0] = r;
            out[ro+1] = g;
            out[ro+2] = bcol;
            size_t po = (size_t)BB*HH*WW*3 + (size_t)(b*HH + y)*WW + x;
            out[po] = 1.0f - pr;
        }
    }
}

extern "C" void kernel_launch(void* const* d_in, const int* in_sizes, int n_in,
                              void* d_out, int out_size)
{
    const float* pts   = (const float*)d_in[0];
    const int*   faces = (const int*)d_in[1];
    const float* rot   = (const float*)d_in[2];
    const float* pos   = (const float*)d_in[3];
    const float* proj  = (const float*)d_in[4];
    const float* cols  = (const float*)d_in[5];
    float* out = (float*)d_out;

    dim3 grid(WW/16, HH/8, BB);   // 14 x 28 x 2 = 784 blocks x 256 threads
    vcr_fused_kernel<<<grid, 256>>>(pts, faces, rot, pos, proj, cols, out);
}

// round 17
// speedup vs baseline: 1.2076x; 1.2076x over previous
#include <cuda_runtime.h>
#include <math.h>

#define HH 224
#define WW 224
#define BB 2
#define PP 2048
#define FF 256
#define SIGMA_F 0.0003f
#define INV_SIGMA 3333.3333333f
// Drop faces whose prob p = exp(-d2/sigma) < 1e-6: each omitted factor
// perturbs prod by < 1e-6 relative; worst case over <= 256 faces < 2.6e-4,
// vs the 1e-3 norm-relative threshold (realistically ~1e-5; measured 4e-7).
#define D2CUT 0.0041447f             // sigma * ln(1e6)
#define MARGIN 0.0643793f            // sqrt(D2CUT)

struct MergeRec { float z, l0, l1, pr; int bi; };

__device__ __forceinline__ void edge_dist(float px, float py, float4 v3,
                                          float4 v4, float4 v5, float4 v6,
                                          float x2, float y2, float& prod)
{
    float pax = px - v3.x, pay = py - v3.y;                 // from v0
    float t = fminf(fmaxf((pax*v4.x + pay*v4.y)*v4.z, 0.0f), 1.0f);
    float ddx = pax - t*v4.x, ddy = pay - t*v4.y;
    float d2 = ddx*ddx + ddy*ddy;

    pax = px - v3.z; pay = py - v3.w;                       // from v1
    t = fminf(fmaxf((pax*v5.x + pay*v5.y)*v5.z, 0.0f), 1.0f);
    ddx = pax - t*v5.x; ddy = pay - t*v5.y;
    d2 = fminf(d2, ddx*ddx + ddy*ddy);

    pax = px - x2; pay = py - y2;                           // from v2
    t = fminf(fmaxf((pax*v6.x + pay*v6.y)*v6.z, 0.0f), 1.0f);
    ddx = pax - t*v6.x; ddy = pay - t*v6.y;
    d2 = fminf(d2, ddx*ddx + ddy*ddy);

    if (d2 < D2CUT) {
        float p = __expf(-d2 * INV_SIGMA) * (1.0f - 1e-7f);
        prod *= fmaxf(1.0f - p, 0.0f);
    }
}

// ---------------------------------------------------------------------------
// Fused kernel: 256 threads/block, 16x8 tile, grid (14, 28, BB).
// Phase 1: thread f computes face f's transform, culls (front & bbox+margin),
//          order-preserving compaction straight into smem.
// Phase 2: 64 pixel-pairs x 4 face-quarters (contiguous ranges).
// Phase 3: quarter merge (buffers overlaid on sf_hot), color gather via vi.
// __launch_bounds__(256, 5): 51-reg cap (compiles to ~48, no spills) ->
// 5 CTA/SM -> 740 resident slots for 784 blocks ~= one wave.
// (256,6) forces 42 regs and SPILLS — measured regression, do not revisit.
// ---------------------------------------------------------------------------
__global__ void __launch_bounds__(256, 5) vcr_fused_kernel(
    const float* __restrict__ pts,
    const int*   __restrict__ faces,
    const float* __restrict__ rot,
    const float* __restrict__ pos,
    const float* __restrict__ proj,
    const float* __restrict__ cols,
    float* __restrict__ out)
{
    __shared__ float4 sf_hot[FF * 3];     // 12 KB; reused as MergeRec after loop
    __shared__ float4 sf_edge[FF * 4];    // 16 KB
    __shared__ int4   svi[FF];            // 4 KB: vertex indices per slot
    __shared__ int    warp_off[8];
    __shared__ int    sm_cnt;

    int b   = blockIdx.z;
    int tid = threadIdx.x;

    int tx0 = blockIdx.x * 16;
    int ty0 = blockIdx.y * 8;
    float txmin = (2.0f*tx0 + 1.0f) * (1.0f/WW) - 1.0f;
    float txmax = (2.0f*(tx0+15) + 1.0f) * (1.0f/WW) - 1.0f;
    float tymax = 1.0f - (2.0f*ty0 + 1.0f) * (1.0f/HH);
    float tymin = 1.0f - (2.0f*(ty0+7) + 1.0f) * (1.0f/HH);

    // ---------------- Phase 1: per-face prep + cull + compact ----------------
    {
        int f = tid;
        float R0 = __ldg(&rot[b*9+0]), R1 = __ldg(&rot[b*9+1]), R2 = __ldg(&rot[b*9+2]);
        float R3 = __ldg(&rot[b*9+3]), R4 = __ldg(&rot[b*9+4]), R5 = __ldg(&rot[b*9+5]);
        float R6 = __ldg(&rot[b*9+6]), R7 = __ldg(&rot[b*9+7]), R8 = __ldg(&rot[b*9+8]);
        float cpx = __ldg(&pos[b*3+0]), cpy = __ldg(&pos[b*3+1]), cpz = __ldg(&pos[b*3+2]);
        float pr0 = __ldg(&proj[0]), pr1 = __ldg(&proj[1]), pr2 = __ldg(&proj[2]);

        int vi0 = __ldg(&faces[f*3+0]);
        int vi1 = __ldg(&faces[f*3+1]);
        int vi2 = __ldg(&faces[f*3+2]);
        int vi[3] = { vi0, vi1, vi2 };

        float Pz[3], Qx[3], Qy[3];
        float nx, ny, nz;
        {
            float Px[3], Py[3];
            #pragma unroll
            for (int k = 0; k < 3; k++) {
                const float* pp = pts + ((size_t)b * PP + vi[k]) * 3;
                float dx = __ldg(pp+0)-cpx, dy = __ldg(pp+1)-cpy, dz = __ldg(pp+2)-cpz;
                float cx = R0*dx + R1*dy + R2*dz;
                float cy = R3*dx + R4*dy + R5*dz;
                float cw = R6*dx + R7*dy + R8*dz;
                Px[k]=cx; Py[k]=cy; Pz[k]=cw;
                float zz = cw * pr2;
                Qx[k] = (cx*pr0)/zz;
                Qy[k] = (cy*pr1)/zz;
            }
            float ux=Px[1]-Px[0], uy=Py[1]-Py[0], uz=Pz[1]-Pz[0];
            float vx=Px[2]-Px[0], vy=Py[2]-Py[0], vz=Pz[2]-Pz[0];
            nx = uy*vz - uz*vy;
            ny = uz*vx - ux*vz;
            nz = ux*vy - uy*vx;
        }

        if (blockIdx.x == 0 && blockIdx.y == 0) {
            float inv = 1.0f / sqrtf(nx*nx + ny*ny + nz*nz + 1e-10f);
            size_t noff = (size_t)BB*HH*WW*3 + (size_t)BB*HH*WW + ((size_t)b*FF + f)*3;
            out[noff+0] = nx*inv;
            out[noff+1] = ny*inv;
            out[noff+2] = nz*inv;
        }

        float bxmin = fminf(Qx[0], fminf(Qx[1], Qx[2]));
        float bxmax = fmaxf(Qx[0], fmaxf(Qx[1], Qx[2]));
        float bymin = fminf(Qy[0], fminf(Qy[1], Qy[2]));
        float bymax = fmaxf(Qy[0], fmaxf(Qy[1], Qy[2]));
        bool keep = (nz > 0.0f) &
                    (bxmin - MARGIN <= txmax) & (bxmax + MARGIN >= txmin) &
                    (bymin - MARGIN <= tymax) & (bymax + MARGIN >= tymin);

        unsigned mask = __ballot_sync(0xffffffffu, keep);
        int lane = tid & 31, wid = tid >> 5;
        if (lane == 0) warp_off[wid] = __popc(mask);
        __syncthreads();
        if (tid == 0) {
            int s = 0;
            #pragma unroll
            for (int i = 0; i < 8; i++) { int t = warp_off[i]; warp_off[i] = s; s += t; }
            sm_cnt = s;
        }
        __syncthreads();

        if (keep) {
            int slot = warp_off[wid] + __popc(mask & ((1u << lane) - 1u));

            float denom = (Qy[1]-Qy[2])*(Qx[0]-Qx[2]) + (Qx[2]-Qx[1])*(Qy[0]-Qy[2]);
            if (fabsf(denom) < 1e-10f) denom = 1e-10f;
            float invden = 1.0f / denom;
            float den2 = denom * denom;

            float e01x = Qx[1]-Qx[0], e01y = Qy[1]-Qy[0];
            float e12x = Qx[2]-Qx[1], e12y = Qy[2]-Qy[1];
            float e20x = Qx[0]-Qx[2], e20y = Qy[0]-Qy[2];
            float i01 = 1.0f/(e01x*e01x + e01y*e01y + 1e-10f);
            float i12 = 1.0f/(e12x*e12x + e12y*e12y + 1e-10f);
            float i20 = 1.0f/(e20x*e20x + e20y*e20y + 1e-10f);

            sf_hot[slot*3+0] = make_float4(Qx[2], Qy[2], (Qy[1]-Qy[2])*invden, (Qx[2]-Qx[1])*invden);
            sf_hot[slot*3+1] = make_float4((Qy[2]-Qy[0])*invden, (Qx[0]-Qx[2])*invden, Pz[0], Pz[1]);
            sf_hot[slot*3+2] = make_float4(Pz[2], den2*i12, den2*i20, den2*i01);
            sf_edge[slot*4+0] = make_float4(Qx[0], Qy[0], Qx[1], Qy[1]);
            sf_edge[slot*4+1] = make_float4(e01x, e01y, i01, 0.0f);
            sf_edge[slot*4+2] = make_float4(e12x, e12y, i12, 0.0f);
            sf_edge[slot*4+3] = make_float4(e20x, e20y, i20, 0.0f);
            svi[slot] = make_int4(vi0, vi1, vi2, 0);
        }
    }
    __syncthreads();
    int m = sm_cnt;

    // ---------------- Phase 2: render 2 px/thread, quarter face ranges -------
    int quarter = tid >> 6;            // 0..3
    int p       = tid & 63;            // pixel pair
    int xa = tx0 + (p & 7) * 2;
    int y  = ty0 + (p >> 3);
    float pxa = (2.0f*xa + 1.0f) * (1.0f/WW) - 1.0f;
    float pxb = pxa + 2.0f*(1.0f/WW);
    float py  = 1.0f - (2.0f*y + 1.0f) * (1.0f/HH);

    const float IN_F = 1.0f - (1.0f - 1e-7f);   // exact (Sterbenz)

    int ibeg = (m * quarter) >> 2;
    int iend = (m * (quarter + 1)) >> 2;

    float besta = -1e10f, bestb = -1e10f;
    int   bia = -1, bib = -1;
    float bl0a = 0.0f, bl1a = 0.0f, bl0b = 0.0f, bl1b = 0.0f;
    float proda = 1.0f, prodb = 1.0f;

    #pragma unroll 2
    for (int i = ibeg; i < iend; i++) {
        float4 v0 = sf_hot[i*3+0];
        float4 v1 = sf_hot[i*3+1];
        float4 v2 = sf_hot[i*3+2];

        float dy  = py  - v0.y;
        float dxa = pxa - v0.x;
        float dxb = pxb - v0.x;
        float t0 = v0.w * dy;
        float t1 = v1.y * dy;
        float l0a = fmaf(v0.z, dxa, t0);
        float l0b = fmaf(v0.z, dxb, t0);
        float l1a = fmaf(v1.x, dxa, t1);
        float l1b = fmaf(v1.x, dxb, t1);
        float l2a = 1.0f - l0a - l1a;
        float l2b = 1.0f - l0b - l1b;

        bool ina = fminf(l0a, fminf(l1a, l2a)) >= 0.0f;
        bool inb = fminf(l0b, fminf(l1b, l2b)) >= 0.0f;
        bool needa = false, needb = false;

        if (ina) {
            float z = l0a*v1.z + l1a*v1.w + l2a*v2.x;
            if (z > besta) { besta = z; bia = i; bl0a = l0a; bl1a = l1a; }
            proda *= IN_F;
        } else {
            float lb2 = 0.0f;
            if (l0a < 0.0f) lb2 = l0a*l0a*v2.y;
            if (l1a < 0.0f) lb2 = fmaxf(lb2, l1a*l1a*v2.z);
            if (l2a < 0.0f) lb2 = fmaxf(lb2, l2a*l2a*v2.w);
            needa = lb2 < D2CUT;
        }
        if (inb) {
            float z = l0b*v1.z + l1b*v1.w + l2b*v2.x;
            if (z > bestb) { bestb = z; bib = i; bl0b = l0b; bl1b = l1b; }
            prodb *= IN_F;
        } else {
            float lb2 = 0.0f;
            if (l0b < 0.0f) lb2 = l0b*l0b*v2.y;
            if (l1b < 0.0f) lb2 = fmaxf(lb2, l1b*l1b*v2.z);
            if (l2b < 0.0f) lb2 = fmaxf(lb2, l2b*l2b*v2.w);
            needb = lb2 < D2CUT;
        }

        if (needa | needb) {
            float4 v3 = sf_edge[i*4+0];
            float4 v4 = sf_edge[i*4+1];
            float4 v5 = sf_edge[i*4+2];
            float4 v6 = sf_edge[i*4+3];
            if (needa) edge_dist(pxa, py, v3, v4, v5, v6, v0.x, v0.y, proda);
            if (needb) edge_dist(pxb, py, v3, v4, v5, v6, v0.x, v0.y, prodb);
        }
    }

    // ---------------- Phase 3: merge (buffers overlay sf_hot) ----------------
    MergeRec* mrec = (MergeRec*)sf_hot;   // 384 recs * 20 B = 7.7 KB <= 12 KB
    __syncthreads();                      // all loop reads of sf_hot done
    if (quarter > 0) {
        int base = (quarter - 1) * 128;
        mrec[base + p]      = { besta, bl0a, bl1a, proda, bia };
        mrec[base + 64 + p] = { bestb, bl0b, bl1b, prodb, bib };
    }
    __syncthreads();
    if (quarter == 0) {
        #pragma unroll
        for (int k = 0; k < 3; k++) {
            MergeRec ra = mrec[k*128 + p];
            if (ra.z > besta) { besta = ra.z; bia = ra.bi; bl0a = ra.l0; bl1a = ra.l1; }
            proda *= ra.pr;
            MergeRec rb = mrec[k*128 + 64 + p];
            if (rb.z > bestb) { bestb = rb.z; bib = rb.bi; bl0b = rb.l0; bl1b = rb.l1; }
            prodb *= rb.pr;
        }

        #pragma unroll
        for (int j = 0; j < 2; j++) {
            int   bi  = j ? bib : bia;
            float bl0 = j ? bl0b : bl0a;
            float bl1 = j ? bl1b : bl1a;
            float pr  = j ? prodb : proda;
            float r = 0.0f, g = 0.0f, bcol = 0.0f;
            if (bi >= 0) {
                float bl2 = 1.0f - bl0 - bl1;
                int4 vi = svi[bi];
                const float* c0 = cols + ((size_t)b * PP + vi.x) * 3;
                const float* c1 = cols + ((size_t)b * PP + vi.y) * 3;
                const float* c2 = cols + ((size_t)b * PP + vi.z) * 3;
                r    = bl0*__ldg(c0+0) + bl1*__ldg(c1+0) + bl2*__ldg(c2+0);
                g    = bl0*__ldg(c0+1) + bl1*__ldg(c1+1) + bl2*__ldg(c2+1);
                bcol = bl0*__ldg(c0+2) + bl1*__ldg(c1+2) + bl2*__ldg(c2+2);
            }
            int x = xa + j;
            size_t ro = ((size_t)(b*HH + y)*WW + x)*3;
            out[ro+0] = r;
            out[ro+1] = g;
            out[ro+2] = bcol;
            size_t po = (size_t)BB*HH*WW*3 + (size_t)(b*HH + y)*WW + x;
            out[po] = 1.0f - pr;
        }
    }
}

extern "C" void kernel_launch(void* const* d_in, const int* in_sizes, int n_in,
                              void* d_out, int out_size)
{
    const float* pts   = (const float*)d_in[0];
    const int*   faces = (const int*)d_in[1];
    const float* rot   = (const float*)d_in[2];
    const float* pos   = (const float*)d_in[3];
    const float* proj  = (const float*)d_in[4];
    const float* cols  = (const float*)d_in[5];
    float* out = (float*)d_out;

    dim3 grid(WW/16, HH/8, BB);   // 14 x 28 x 2 = 784 blocks x 256 threads
    vcr_fused_kernel<<<grid, 256>>>(pts, faces, rot, pos, proj, cols, out);
}